// round 14
// baseline (speedup 1.0000x reference)
#include <cuda_runtime.h>
#include <cstdint>

// Problem constants
#define BB 4
#define SS 512     // SX == SY
#define HH 128     // H
#define DD 256     // 2H

// Scratch for projections (no cudaMalloc allowed)
__device__ float g_s1[BB * SS * HH];   // s1[b,s,h]
__device__ float g_s2[BB * SS * HH];   // s2[b,t,h]

__device__ __forceinline__ float tanh_fast(float v) {
    float r;
    asm("tanh.approx.f32 %0, %1;" : "=f"(r) : "f"(v));
    return r;
}

// ---------------------------------------------------------------------------
// Kernel A: projections. s1 = x @ W1^T, s2 = y @ W2^T
// grid = 128 CTAs (64 per projection), 256 threads.
// Per CTA: 32 rows x 128 h, full K=256 with W transposed in smem [k][h].
// ---------------------------------------------------------------------------
#define GA_THREADS 256
#define WPITCH 132     // padded k-row pitch (multiple of 4 for float4 loads)

__global__ __launch_bounds__(GA_THREADS)
void proj_kernel(const float* __restrict__ x, const float* __restrict__ y,
                 const float* __restrict__ W1, const float* __restrict__ W2)
{
    extern __shared__ float sm[];
    float* Wsm   = sm;                    // [256][WPITCH]  (Wsm[k][h] = W[h][k])
    float* rowsm = sm + 256 * WPITCH;     // [32][256]

    const int part = blockIdx.x >> 6;     // 0: x->s1, 1: y->s2
    const int cta  = blockIdx.x & 63;
    const float* W   = part ? W2 : W1;
    const float* src = part ? y  : x;
    float* dst = part ? g_s2 : g_s1;

    const int tid = threadIdx.x;

    // Load + transpose W into Wsm[k][h]. Lanes vary over h -> conflict-free STS.
    {
        const float4* W4 = (const float4*)W;      // W is [128][256] row-major
        const int h   = tid & 127;
        const int kq0 = tid >> 7;                 // 0 or 1
        #pragma unroll
        for (int i = 0; i < 32; i++) {
            const int kq = kq0 + 2 * i;           // float4 index along k, 0..63
            float4 wv = W4[h * 64 + kq];
            Wsm[(4 * kq + 0) * WPITCH + h] = wv.x;
            Wsm[(4 * kq + 1) * WPITCH + h] = wv.y;
            Wsm[(4 * kq + 2) * WPITCH + h] = wv.z;
            Wsm[(4 * kq + 3) * WPITCH + h] = wv.w;
        }
    }

    // Load 32 input rows (contiguous copy).
    const int r0 = cta * 32;                      // global row in the 2048-row matrix
    {
        const float4* s4 = (const float4*)(src + (size_t)r0 * DD);
        float4* d4 = (float4*)rowsm;
        #pragma unroll
        for (int i = 0; i < 8; i++)
            d4[tid + GA_THREADS * i] = s4[tid + GA_THREADS * i];
    }
    __syncthreads();

    const int w = tid >> 5, lane = tid & 31;
    float4 a0 = {0,0,0,0}, a1 = {0,0,0,0}, a2 = {0,0,0,0}, a3 = {0,0,0,0};
    const float* rb = rowsm + (w * 4) * DD;       // 4 rows per warp

    #pragma unroll 4
    for (int k = 0; k < DD; k++) {
        float4 wv = *(const float4*)&Wsm[k * WPITCH + lane * 4];
        float x0 = rb[k];
        float x1 = rb[DD + k];
        float x2 = rb[2 * DD + k];
        float x3 = rb[3 * DD + k];
        a0.x += x0 * wv.x; a0.y += x0 * wv.y; a0.z += x0 * wv.z; a0.w += x0 * wv.w;
        a1.x += x1 * wv.x; a1.y += x1 * wv.y; a1.z += x1 * wv.z; a1.w += x1 * wv.w;
        a2.x += x2 * wv.x; a2.y += x2 * wv.y; a2.z += x2 * wv.z; a2.w += x2 * wv.w;
        a3.x += x3 * wv.x; a3.y += x3 * wv.y; a3.z += x3 * wv.z; a3.w += x3 * wv.w;
    }

    ((float4*)(dst + (size_t)(r0 + w * 4 + 0) * HH))[lane] = a0;
    ((float4*)(dst + (size_t)(r0 + w * 4 + 1) * HH))[lane] = a1;
    ((float4*)(dst + (size_t)(r0 + w * 4 + 2) * HH))[lane] = a2;
    ((float4*)(dst + (size_t)(r0 + w * 4 + 3) * HH))[lane] = a3;
}

// ---------------------------------------------------------------------------
// Kernel B: fused score + softmax + weighted sum.
// grid = (SY/TY, B) = (64, 4), 256 threads (8 warps), warp w owns t = t0 + w.
// Pass 1: per warp, lane = s within a 32-wide s-block staged in smem;
//         128 tanh per score, MUFU-bound.
// Pass 2: x tile staged in smem, shared by all 8 warps.
// ---------------------------------------------------------------------------
#define TY 8
#define AT_THREADS 256
#define S2P 132                                   // padded pitch

#define V_OFF   (TY * S2P)                        // 1056
#define SC_OFF  (V_OFF + 128)                     // 1184
#define BUF_OFF (SC_OFF + TY * 512)               // 5280
#define SM_FLOATS (BUF_OFF + 32 * 256)            // 13472 floats = 53888 B

__global__ __launch_bounds__(AT_THREADS)
void attn_kernel(const float* __restrict__ x, const float* __restrict__ vc,
                 float* __restrict__ out)
{
    extern __shared__ float sm[];
    float* s2sm = sm;               // [TY][S2P]
    float* vsm  = sm + V_OFF;       // [128]
    float* scsm = sm + SC_OFF;      // [TY][512]
    float* buf  = sm + BUF_OFF;     // pass1: s1 tile [32][S2P]; pass2: x tile [32][256]

    const int b  = blockIdx.y;
    const int t0 = blockIdx.x * TY;
    const int tid = threadIdx.x, w = tid >> 5, lane = tid & 31;

    // Load s2 rows for this t-tile and v (visible after first __syncthreads).
    {
        const int r = tid >> 5, c4 = tid & 31;
        *(float4*)&s2sm[r * S2P + c4 * 4] =
            *(const float4*)&g_s2[(size_t)(b * SS + t0 + r) * HH + c4 * 4];
        if (tid < 32)
            *(float4*)&vsm[tid * 4] = *(const float4*)&vc[tid * 4];
    }

    // ---- Pass 1: scores -----------------------------------------------------
    float sc[16];
    const float* s2r = s2sm + w * S2P;

    for (int sb = 0; sb < 16; sb++) {
        __syncthreads();
        // Stage s1 tile [32 s][128 h] padded to S2P.
        #pragma unroll
        for (int i = 0; i < 4; i++) {
            const int f = tid + AT_THREADS * i;      // 0..1023 float4s
            const int r = f >> 5, c4 = f & 31;
            *(float4*)&buf[r * S2P + c4 * 4] =
                *(const float4*)&g_s1[(size_t)(b * SS + sb * 32 + r) * HH + c4 * 4];
        }
        __syncthreads();

        float s = 0.0f;
        const float* a = buf + lane * S2P;           // lane's s row (conflict-free, pad 132)
        #pragma unroll 8
        for (int h4 = 0; h4 < 32; h4++) {
            float4 av = *(const float4*)&a[h4 * 4];
            float4 bv = *(const float4*)&s2r[h4 * 4];   // broadcast
            float4 vv = *(const float4*)&vsm[h4 * 4];   // broadcast
            s += tanh_fast(av.x + bv.x) * vv.x;
            s += tanh_fast(av.y + bv.y) * vv.y;
            s += tanh_fast(av.z + bv.z) * vv.z;
            s += tanh_fast(av.w + bv.w) * vv.w;
        }
        sc[sb] = s;
    }

    // ---- Softmax over the 512 scores (warp-local) ---------------------------
    float m = sc[0];
    #pragma unroll
    for (int i = 1; i < 16; i++) m = fmaxf(m, sc[i]);
    #pragma unroll
    for (int o = 16; o > 0; o >>= 1) m = fmaxf(m, __shfl_xor_sync(0xffffffffu, m, o));

    float sum = 0.0f;
    #pragma unroll
    for (int i = 0; i < 16; i++) { sc[i] = __expf(sc[i] - m); sum += sc[i]; }
    #pragma unroll
    for (int o = 16; o > 0; o >>= 1) sum += __shfl_xor_sync(0xffffffffu, sum, o);

    const float inv = 1.0f / sum;
    #pragma unroll
    for (int i = 0; i < 16; i++) scsm[w * 512 + i * 32 + lane] = sc[i] * inv;

    // ---- Pass 2: out[t,:] = sum_s w[s] * x[b,s,:] ---------------------------
    float4 acc0 = {0,0,0,0}, acc1 = {0,0,0,0};
    for (int sb = 0; sb < 16; sb++) {
        __syncthreads();   // all warps done reading buf (pass1/prev tile) before overwrite
        const float4* xs = (const float4*)(x + (size_t)(b * SS + sb * 32) * DD);
        float4* bd = (float4*)buf;
        #pragma unroll
        for (int i = 0; i < 8; i++)
            bd[tid + AT_THREADS * i] = xs[tid + AT_THREADS * i];
        __syncthreads();

        const float* wr = scsm + w * 512 + sb * 32;
        #pragma unroll 8
        for (int j = 0; j < 32; j++) {
            const float wt = wr[j];                              // broadcast
            float4 xa = *(const float4*)&buf[j * DD + lane * 4];        // stride-4, CF
            float4 xb = *(const float4*)&buf[j * DD + 128 + lane * 4];  // stride-4, CF
            acc0.x += wt * xa.x; acc0.y += wt * xa.y;
            acc0.z += wt * xa.z; acc0.w += wt * xa.w;
            acc1.x += wt * xb.x; acc1.y += wt * xb.y;
            acc1.z += wt * xb.z; acc1.w += wt * xb.w;
        }
    }

    float* o = out + (size_t)(b * SS + t0 + w) * DD;
    *(float4*)&o[lane * 4]       = acc0;
    *(float4*)&o[128 + lane * 4] = acc1;
}

// ---------------------------------------------------------------------------
extern "C" void kernel_launch(void* const* d_in, const int* in_sizes, int n_in,
                              void* d_out, int out_size)
{
    const float* x   = (const float*)d_in[0];   // (4,512,256)
    const float* y   = (const float*)d_in[1];   // (4,512,256)
    const float* W1  = (const float*)d_in[2];   // (128,256)
    const float* W2  = (const float*)d_in[3];   // (128,256)
    const float* vc  = (const float*)d_in[4];   // (1,128)
    float* out = (float*)d_out;                 // (4,512,256)

    const size_t smA = (size_t)(256 * WPITCH + 32 * 256) * sizeof(float); // ~164 KB
    const size_t smB = (size_t)SM_FLOATS * sizeof(float);                 // ~53 KB

    cudaFuncSetAttribute(proj_kernel, cudaFuncAttributeMaxDynamicSharedMemorySize, (int)smA);
    cudaFuncSetAttribute(attn_kernel, cudaFuncAttributeMaxDynamicSharedMemorySize, (int)smB);

    proj_kernel<<<128, GA_THREADS, smA>>>(x, y, W1, W2);
    attn_kernel<<<dim3(SS / TY, BB), AT_THREADS, smB>>>(x, vc, out);
}